// round 4
// baseline (speedup 1.0000x reference)
#include <cuda_runtime.h>
#include <math.h>
#include <float.h>

#define HID 128

// ---------------- problem constants ----------------
#define N0 100000
#define N1 50000
#define N2 5000
#define NTOT (N0 + N1 + N2)
#define ETOT 900000

static const int EDGE_SRC[5] = {1, 0, 0, 1, 2};
static const int EDGE_DST[5] = {0, 0, 1, 2, 1};
static const int EDGE_CNT[5] = {250000, 250000, 200000, 100000, 100000};
static const int EOFF[5]     = {0, 250000, 500000, 700000, 800000};
static const int NODE_N_[3]  = {N0, N1, N2};
static const int NODE_OFF_[3]= {0, N0, N0 + N1};
static const int IN_DIM_[3]  = {256, 128, 64};

// ---------------- device scratch (static globals; no runtime allocation) ----
__device__ float g_XS0[(size_t)NTOT * HID];
__device__ float g_XS1[(size_t)NTOT * HID];
__device__ float g_CAT[(size_t)N0 * 640 + (size_t)N1 * 640 + (size_t)N2 * 384];
__device__ float g_SC [(size_t)ETOT * 8];
__device__ float g_M  [(size_t)NTOT * 8];
__device__ float g_DEN[(size_t)NTOT * 8];
__device__ float g_AGG[(size_t)NTOT * 128];
__device__ float g_WCAT[HID * 1664];
__device__ float g_BCAT[1664];

// ---------------- device helpers ----------------
__device__ __forceinline__ float gelu_f(float x) {
    return 0.5f * x * (1.0f + erff(x * 0.70710678118654752440f));
}

__device__ __forceinline__ void atomic_max_f(float* addr, float v) {
    if (v >= 0.0f) atomicMax((int*)addr, __float_as_int(v));
    else           atomicMin((unsigned int*)addr, __float_as_uint(v));
}

// ---------------- generic fp32 SGEMM: C = epilogue(preact(A) @ W + bias) ----
// A: [M,K] lda ; W: [K,N] ldw ; C: [M,N] ldc. Requires K % 16 == 0, N % 64 == 0.
template <int PRE_GELU, int RELU, int SKIP>
__global__ __launch_bounds__(256) void sgemm_kernel(
    const float* __restrict__ A, int lda,
    const float* __restrict__ W, int ldw,
    const float* __restrict__ bias,
    float* __restrict__ C, int ldc,
    int M, int N, int K,
    const float* __restrict__ skip_p,
    const float* __restrict__ Xprev, int ldx)
{
    __shared__ float As[16][128];
    __shared__ float Bs[16][64];
    const int tid = threadIdx.x;
    const int bm = blockIdx.x * 128;
    const int bn = blockIdx.y * 64;
    const int tx = tid & 15;
    const int ty = tid >> 4;

    float acc[8][4];
#pragma unroll
    for (int i = 0; i < 8; ++i)
#pragma unroll
        for (int j = 0; j < 4; ++j) acc[i][j] = 0.0f;

    const int nk = K >> 4;
    for (int kt = 0; kt < nk; ++kt) {
        const int k0 = kt << 4;
        // load A tile (128x16) as 512 float4s, 2 per thread
#pragma unroll
        for (int it = 0; it < 2; ++it) {
            int id = tid + it * 256;
            int r  = id >> 2;
            int cs = (id & 3) << 2;
            float4 v = make_float4(0.f, 0.f, 0.f, 0.f);
            int gr = bm + r;
            if (gr < M) v = *(const float4*)(A + (size_t)gr * lda + k0 + cs);
            if (PRE_GELU) {
                v.x = gelu_f(v.x); v.y = gelu_f(v.y);
                v.z = gelu_f(v.z); v.w = gelu_f(v.w);
            }
            As[cs + 0][r] = v.x; As[cs + 1][r] = v.y;
            As[cs + 2][r] = v.z; As[cs + 3][r] = v.w;
        }
        // load B tile (16x64) as 256 float4s, 1 per thread
        {
            int r  = tid >> 4;
            int cs = (tid & 15) << 2;
            float4 v = *(const float4*)(W + (size_t)(k0 + r) * ldw + bn + cs);
            *(float4*)&Bs[r][cs] = v;
        }
        __syncthreads();
#pragma unroll
        for (int k = 0; k < 16; ++k) {
            float a[8], b[4];
            *(float4*)(a)     = *(const float4*)&As[k][ty * 8];
            *(float4*)(a + 4) = *(const float4*)&As[k][ty * 8 + 4];
            *(float4*)(b)     = *(const float4*)&Bs[k][tx * 4];
#pragma unroll
            for (int i = 0; i < 8; ++i)
#pragma unroll
                for (int j = 0; j < 4; ++j) acc[i][j] = fmaf(a[i], b[j], acc[i][j]);
        }
        __syncthreads();
    }

    float ask = 0.0f;
    if (SKIP) ask = 1.0f / (1.0f + expf(-*skip_p));
#pragma unroll
    for (int i = 0; i < 8; ++i) {
        int gr = bm + ty * 8 + i;
        if (gr >= M) continue;
#pragma unroll
        for (int j = 0; j < 4; ++j) {
            int gc = bn + tx * 4 + j;
            float v = acc[i][j] + bias[gc];
            if (RELU) v = fmaxf(v, 0.0f);
            if (SKIP) v = ask * v + (1.0f - ask) * Xprev[(size_t)gr * ldx + gc];
            C[(size_t)gr * ldc + gc] = v;
        }
    }
}

// ---------------- weight-folding kernels ----------------
// Copy q columns of kqv_w[t] (cols F..2F) into Wcat; bias row too.
__global__ void copy_q_kernel(const float* __restrict__ w, const float* __restrict__ b,
                              float* __restrict__ Wcat, float* __restrict__ bcat,
                              int F, int F3, int ncols)
{
    int idx = blockIdx.x * blockDim.x + threadIdx.x;
    int total = (HID + 1) * F;
    if (idx >= total) return;
    int i = idx / F, c = idx - (idx / F) * F;
    if (i < HID) Wcat[i * ncols + c] = w[i * F3 + F + c];
    else         bcat[c] = b[F + c];
}

// Fold per-head dh x dh relation matrix into a kqv weight block:
// out[i, h*16+j] = sum_d w[i, cb + h*16 + d] * rel[h,d,j]
__global__ void build_rel_kernel(const float* __restrict__ w, const float* __restrict__ b,
                                 const float* __restrict__ rel,
                                 float* __restrict__ Wcat, float* __restrict__ bcat,
                                 int F, int F3, int ncols, int cb)
{
    int idx = blockIdx.x * blockDim.x + threadIdx.x;
    int total = (HID + 1) * F;
    if (idx >= total) return;
    int i = idx / F, c = idx - (idx / F) * F;
    int h = c >> 4, j = c & 15;
    const float* src = (i < HID) ? (w + i * F3 + cb) : (b + cb);
    const float* rm = rel + h * 256 + j;
    float acc = 0.0f;
#pragma unroll
    for (int d = 0; d < 16; ++d) acc += src[h * 16 + d] * rm[d * 16];
    if (i < HID) Wcat[i * ncols + c] = acc;
    else         bcat[c] = acc;
}

// ---------------- fills ----------------
__global__ void fill_kernel(float* __restrict__ p, float v, int n)
{
    int i = blockIdx.x * blockDim.x + threadIdx.x;
    if (i < n) p[i] = v;
}

// ---------------- edge kernels ----------------
__global__ void score_kernel(const int* __restrict__ ei, int E,
                             const float* __restrict__ qb, int ldq,
                             const float* __restrict__ kb, int ldk,
                             const float* __restrict__ prel, int H,
                             float* __restrict__ sc, float* __restrict__ mbuf)
{
    int idx = blockIdx.x * blockDim.x + threadIdx.x;
    if (idx >= E * H) return;
    int e = idx / H, h = idx - e * H;
    int src = ei[e], dst = ei[E + e];
    const float4* q = (const float4*)(qb + (size_t)dst * ldq + h * 16);
    const float4* k = (const float4*)(kb + (size_t)src * ldk + h * 16);
    float s = 0.0f;
#pragma unroll
    for (int r = 0; r < 4; ++r) {
        float4 a = q[r], b = k[r];
        s += a.x * b.x + a.y * b.y + a.z * b.z + a.w * b.w;
    }
    s *= prel[h] * 0.25f;   // prel / sqrt(dh), dh = 16
    sc[idx] = s;
    atomic_max_f(&mbuf[(size_t)dst * H + h], s);
}

__global__ void expden_kernel(const int* __restrict__ ei, int E, int H,
                              const float* __restrict__ mbuf,
                              float* __restrict__ sc, float* __restrict__ den)
{
    int idx = blockIdx.x * blockDim.x + threadIdx.x;
    if (idx >= E * H) return;
    int e = idx / H, h = idx - e * H;
    int dst = ei[E + e];
    float ex = expf(sc[idx] - mbuf[(size_t)dst * H + h]);
    sc[idx] = ex;
    atomicAdd(&den[(size_t)dst * H + h], ex);
}

__global__ void agg_kernel(const int* __restrict__ ei, int E, int H, int F,
                           const float* __restrict__ vb, int ldv,
                           const float* __restrict__ sc, const float* __restrict__ den,
                           float* __restrict__ agg)
{
    int f4n = F >> 2;
    int idx = blockIdx.x * blockDim.x + threadIdx.x;
    if (idx >= E * f4n) return;
    int e = idx / f4n, f4 = idx - e * f4n;
    int h = f4 >> 2;
    int src = ei[e], dst = ei[E + e];
    float alpha = sc[(size_t)e * H + h] / fmaxf(den[(size_t)dst * H + h], 1e-16f);
    float4 v = *(const float4*)(vb + (size_t)src * ldv + f4 * 4);
    float* p = agg + (size_t)dst * F + f4 * 4;
    atomicAdd(p + 0, v.x * alpha);
    atomicAdd(p + 1, v.y * alpha);
    atomicAdd(p + 2, v.z * alpha);
    atomicAdd(p + 3, v.w * alpha);
}

// ---------------- host-side layer driver ----------------
struct Scratch {
    float *XS0, *XS1, *CAT, *SC, *M, *DEN, *AGG, *WCAT, *BCAT;
};

static void run_hgt_layer(const Scratch& S,
                          int F, int H,
                          const float* kqvw, const float* kqvb,
                          const float* krel, const float* vrel,
                          const float* prel, const float* outw, const float* outb,
                          const float* skip,
                          const float* xs_in, float* out_base, bool final_layer,
                          const int* const* EIp)
{
    const int F3 = 3 * F;
    const int ncols[3] = {5 * F, 5 * F, 3 * F};
    const size_t cbase[3] = {0,
                             (size_t)N0 * ncols[0],
                             (size_t)N0 * ncols[0] + (size_t)N1 * ncols[1]};
    const int wbase[3] = {0, HID * ncols[0], HID * (ncols[0] + ncols[1])};
    const int bbase[3] = {0, ncols[0], ncols[0] + ncols[1]};
    const int koff_e[5] = {F, F, 3 * F, 3 * F, F};

    // 1. build concatenated [q | k_rel | v_rel] weights
    {
        int tot = (HID + 1) * F;
        int blk = (tot + 255) / 256;
        for (int t = 0; t < 3; ++t)
            copy_q_kernel<<<blk, 256>>>(kqvw + (size_t)t * HID * F3, kqvb + (size_t)t * F3,
                                        S.WCAT + wbase[t], S.BCAT + bbase[t],
                                        F, F3, ncols[t]);
        for (int e = 0; e < 5; ++e) {
            int t = EDGE_SRC[e];
            build_rel_kernel<<<blk, 256>>>(kqvw + (size_t)t * HID * F3, kqvb + (size_t)t * F3,
                                           krel + (size_t)e * H * 256,
                                           S.WCAT + wbase[t] + koff_e[e],
                                           S.BCAT + bbase[t] + koff_e[e],
                                           F, F3, ncols[t], 0);
            build_rel_kernel<<<blk, 256>>>(kqvw + (size_t)t * HID * F3, kqvb + (size_t)t * F3,
                                           vrel + (size_t)e * H * 256,
                                           S.WCAT + wbase[t] + koff_e[e] + F,
                                           S.BCAT + bbase[t] + koff_e[e] + F,
                                           F, F3, ncols[t], 2 * F);
        }
    }

    // 2. fused KQV+relation GEMMs
    for (int t = 0; t < 3; ++t) {
        dim3 g((NODE_N_[t] + 127) / 128, ncols[t] / 64);
        sgemm_kernel<0, 0, 0><<<g, 256>>>(xs_in + (size_t)NODE_OFF_[t] * HID, HID,
                                          S.WCAT + wbase[t], ncols[t], S.BCAT + bbase[t],
                                          S.CAT + cbase[t], ncols[t],
                                          NODE_N_[t], ncols[t], HID,
                                          nullptr, nullptr, 0);
    }

    // 3. init softmax state
    {
        int n1 = NTOT * H;
        fill_kernel<<<(n1 + 255) / 256, 256>>>(S.M, -FLT_MAX, n1);
        fill_kernel<<<(n1 + 255) / 256, 256>>>(S.DEN, 0.0f, n1);
        int n2 = NTOT * F;
        fill_kernel<<<(n2 + 255) / 256, 256>>>(S.AGG, 0.0f, n2);
    }

    // 4. edge passes
    for (int e = 0; e < 5; ++e) {
        int ts = EDGE_SRC[e], td = EDGE_DST[e], E = EDGE_CNT[e];
        int n = E * H;
        score_kernel<<<(n + 255) / 256, 256>>>(
            EIp[e], E,
            S.CAT + cbase[td], ncols[td],
            S.CAT + cbase[ts] + koff_e[e], ncols[ts],
            prel + (size_t)e * H, H,
            S.SC + (size_t)EOFF[e] * H,
            S.M + (size_t)NODE_OFF_[td] * H);
    }
    for (int e = 0; e < 5; ++e) {
        int td = EDGE_DST[e], E = EDGE_CNT[e];
        int n = E * H;
        expden_kernel<<<(n + 255) / 256, 256>>>(
            EIp[e], E, H,
            S.M + (size_t)NODE_OFF_[td] * H,
            S.SC + (size_t)EOFF[e] * H,
            S.DEN + (size_t)NODE_OFF_[td] * H);
    }
    for (int e = 0; e < 5; ++e) {
        int ts = EDGE_SRC[e], td = EDGE_DST[e], E = EDGE_CNT[e];
        int n = E * (F / 4);
        agg_kernel<<<(n + 255) / 256, 256>>>(
            EIp[e], E, H, F,
            S.CAT + cbase[ts] + koff_e[e] + F, ncols[ts],
            S.SC + (size_t)EOFF[e] * H,
            S.DEN + (size_t)NODE_OFF_[td] * H,
            S.AGG + (size_t)NODE_OFF_[td] * F);
    }

    // 5. output projection: gelu(agg) @ out_w + b (+ skip blend on layer 1)
    for (int t = 0; t < 3; ++t) {
        dim3 g((NODE_N_[t] + 127) / 128, F / 64);
        if (!final_layer) {
            sgemm_kernel<1, 0, 1><<<g, 256>>>(S.AGG + (size_t)NODE_OFF_[t] * F, F,
                                              outw + (size_t)t * F * F, F, outb + (size_t)t * F,
                                              out_base + (size_t)NODE_OFF_[t] * HID, HID,
                                              NODE_N_[t], F, F,
                                              skip + t, xs_in + (size_t)NODE_OFF_[t] * HID, HID);
        } else {
            sgemm_kernel<1, 0, 0><<<g, 256>>>(S.AGG + (size_t)NODE_OFF_[t] * F, F,
                                              outw + (size_t)t * F * F, F, outb + (size_t)t * F,
                                              out_base + (size_t)NODE_OFF_[t] * F, F,
                                              NODE_N_[t], F, F,
                                              nullptr, nullptr, 0);
        }
    }
}

// ---------------- entry point ----------------
extern "C" void kernel_launch(void* const* d_in, const int* in_sizes, int n_in,
                              void* d_out, int out_size)
{
    // Resolve input ordering at runtime: reference-signature order has lin_w_p
    // (256*128 = 32768 elems) at index 3; setup-dict order has ei0 (500000) there.
    int xp, xa, xi, lwp, lbp, lwa, lba, lwi, lbi;
    int kw1, kb1, kr1, vr1, pr1, ow1, ob1, sk1;
    int kw2, kb2, kr2, vr2, pr2, ow2, ob2, sk2;
    int eix[5];
    if (n_in > 3 && in_sizes[3] == 32768) {
        xp = 0; xa = 1; xi = 2;
        lwp = 3; lbp = 4; lwa = 5; lba = 6; lwi = 7; lbi = 8;
        kw1 = 9; kb1 = 10; kr1 = 11; vr1 = 12; pr1 = 13; ow1 = 14; ob1 = 15; sk1 = 16;
        kw2 = 17; kb2 = 18; kr2 = 19; vr2 = 20; pr2 = 21; ow2 = 22; ob2 = 23; sk2 = 24;
        eix[0] = 25; eix[1] = 26; eix[2] = 27; eix[3] = 28; eix[4] = 29;
    } else {
        xp = 0; xa = 1; xi = 2;
        eix[0] = 3; eix[1] = 4; eix[2] = 5; eix[3] = 6; eix[4] = 7;
        lwp = 8; lbp = 9; lwa = 10; lba = 11; lwi = 12; lbi = 13;
        kw1 = 14; kb1 = 15; kr1 = 16; vr1 = 17; pr1 = 18; ow1 = 19; ob1 = 20; sk1 = 21;
        kw2 = 22; kb2 = 23; kr2 = 24; vr2 = 25; pr2 = 26; ow2 = 27; ob2 = 28; sk2 = 29;
    }

    Scratch S;
    cudaGetSymbolAddress((void**)&S.XS0, g_XS0);
    cudaGetSymbolAddress((void**)&S.XS1, g_XS1);
    cudaGetSymbolAddress((void**)&S.CAT, g_CAT);
    cudaGetSymbolAddress((void**)&S.SC,  g_SC);
    cudaGetSymbolAddress((void**)&S.M,   g_M);
    cudaGetSymbolAddress((void**)&S.DEN, g_DEN);
    cudaGetSymbolAddress((void**)&S.AGG, g_AGG);
    cudaGetSymbolAddress((void**)&S.WCAT, g_WCAT);
    cudaGetSymbolAddress((void**)&S.BCAT, g_BCAT);

    const float* X[3]  = {(const float*)d_in[xp], (const float*)d_in[xa], (const float*)d_in[xi]};
    const float* LW[3] = {(const float*)d_in[lwp], (const float*)d_in[lwa], (const float*)d_in[lwi]};
    const float* LB[3] = {(const float*)d_in[lbp], (const float*)d_in[lba], (const float*)d_in[lbi]};
    const int* EIp[5];
    for (int e = 0; e < 5; ++e) EIp[e] = (const int*)d_in[eix[e]];

    // input projections + relu -> XS0
    for (int t = 0; t < 3; ++t) {
        dim3 g((NODE_N_[t] + 127) / 128, HID / 64);
        sgemm_kernel<0, 1, 0><<<g, 256>>>(X[t], IN_DIM_[t], LW[t], HID, LB[t],
                                          S.XS0 + (size_t)NODE_OFF_[t] * HID, HID,
                                          NODE_N_[t], HID, IN_DIM_[t],
                                          nullptr, nullptr, 0);
    }

    // layer 1: hidden 128, heads 8, skip blend, XS0 -> XS1
    run_hgt_layer(S, 128, 8,
                  (const float*)d_in[kw1], (const float*)d_in[kb1],
                  (const float*)d_in[kr1], (const float*)d_in[vr1],
                  (const float*)d_in[pr1], (const float*)d_in[ow1],
                  (const float*)d_in[ob1], (const float*)d_in[sk1],
                  S.XS0, S.XS1, false, EIp);

    // layer 2: out 64, heads 4, no skip, XS1 -> d_out
    run_hgt_layer(S, 64, 4,
                  (const float*)d_in[kw2], (const float*)d_in[kb2],
                  (const float*)d_in[kr2], (const float*)d_in[vr2],
                  (const float*)d_in[pr2], (const float*)d_in[ow2],
                  (const float*)d_in[ob2], (const float*)d_in[sk2],
                  S.XS1, (float*)d_out, true, EIp);

    (void)out_size;
}

// round 6
// speedup vs baseline: 1.4613x; 1.4613x over previous
#include <cuda_runtime.h>
#include <math.h>
#include <float.h>
#include <stdint.h>

#define HID 128

// ---------------- problem constants ----------------
#define N0 100000
#define N1 50000
#define N2 5000
#define NTOT (N0 + N1 + N2)
#define ETOT 900000

static const int EDGE_SRC[5] = {1, 0, 0, 1, 2};
static const int EDGE_DST[5] = {0, 0, 1, 2, 1};
static const int EDGE_CNT[5] = {250000, 250000, 200000, 100000, 100000};
static const int EOFF[5]     = {0, 250000, 500000, 700000, 800000};
static const int NODE_N_[3]  = {N0, N1, N2};
static const int NODE_OFF_[3]= {0, N0, N0 + N1};
static const int IN_DIM_[3]  = {256, 128, 64};

// ---------------- device scratch ----------------
__device__ float g_XS0[(size_t)NTOT * HID];
__device__ float g_XS1[(size_t)NTOT * HID];
__device__ float g_CAT[(size_t)N0 * 640 + (size_t)N1 * 640 + (size_t)N2 * 384];
__device__ float g_SC [(size_t)ETOT * 8];
__device__ float g_M  [(size_t)NTOT * 8];
__device__ float g_DEN[(size_t)NTOT * 8];
__device__ float g_AGG[(size_t)NTOT * 128];
__device__ float g_WCAT[HID * 1664];
__device__ float g_BCAT[1664];
__device__ float g_WT[262144];   // transposed tf32 weights, reused sequentially

// ---------------- device helpers ----------------
__device__ __forceinline__ float gelu_f(float x) {
    return 0.5f * x * (1.0f + erff(x * 0.70710678118654752440f));
}
__device__ __forceinline__ float tf32r(float x) {
    float y;
    asm("cvt.rna.tf32.f32 %0, %1;" : "=f"(y) : "f"(x));
    return y;
}
__device__ __forceinline__ void atomic_max_f(float* addr, float v) {
    if (v >= 0.0f) atomicMax((int*)addr, __float_as_int(v));
    else           atomicMin((unsigned int*)addr, __float_as_uint(v));
}

__device__ __forceinline__ void mma_tf32(float* d, const uint32_t* a, const uint32_t* b) {
    asm volatile(
        "mma.sync.aligned.m16n8k8.row.col.f32.tf32.tf32.f32 "
        "{%0,%1,%2,%3}, {%4,%5,%6,%7}, {%8,%9}, {%0,%1,%2,%3};\n"
        : "+f"(d[0]), "+f"(d[1]), "+f"(d[2]), "+f"(d[3])
        : "r"(a[0]), "r"(a[1]), "r"(a[2]), "r"(a[3]), "r"(b[0]), "r"(b[1]));
}

// ---------------- tf32 mma.sync GEMM ----------------
// C[M,N] = epi( preact(A[M,K]) @ WT^T + bias ), WT is [N,K] tf32-rounded.
// CTA tile 128x64, 8 warps (4m x 2n), each warp 32x32 (2 m-frag x 4 n-frag).
// K chunked at 32. SMEM row stride 36 -> frag-load bank = (4r+c)%32, conflict-free.
#define CK 32
#define APAD 36

template <int PRE_GELU, int RELU, int SKIP>
__global__ __launch_bounds__(256)
void mma_gemm(const float* __restrict__ A, int lda,
              const float* __restrict__ WT, int K,
              const float* __restrict__ bias,
              float* __restrict__ C, int ldc, int M,
              const float* __restrict__ skip_p,
              const float* __restrict__ Xprev, int ldx)
{
    __shared__ float As[128 * APAD];
    __shared__ float Bs[64 * APAD];
    const int tid = threadIdx.x;
    const int wid = tid >> 5, lane = tid & 31;
    const int grp = lane >> 2, qid = lane & 3;
    const int wm = wid & 3, wn = wid >> 2;
    const int bm = blockIdx.x * 128, bn = blockIdx.y * 64;

    float d[2][4][4];
#pragma unroll
    for (int mi = 0; mi < 2; ++mi)
#pragma unroll
        for (int ni = 0; ni < 4; ++ni)
#pragma unroll
            for (int q = 0; q < 4; ++q) d[mi][ni][q] = 0.0f;

    for (int k0 = 0; k0 < K; k0 += CK) {
        // ---- stage A chunk 128 x 32 (1024 float4, 4/thread) ----
#pragma unroll
        for (int it = 0; it < 4; ++it) {
            int idx = tid + it * 256;
            int r = idx >> 3, c4 = (idx & 7) << 2;
            float4 v = make_float4(0.f, 0.f, 0.f, 0.f);
            int gr = bm + r;
            if (gr < M) v = *(const float4*)(A + (size_t)gr * lda + k0 + c4);
            if (PRE_GELU) {
                v.x = gelu_f(v.x); v.y = gelu_f(v.y);
                v.z = gelu_f(v.z); v.w = gelu_f(v.w);
            }
            v.x = tf32r(v.x); v.y = tf32r(v.y); v.z = tf32r(v.z); v.w = tf32r(v.w);
            *(float4*)&As[r * APAD + c4] = v;
        }
        // ---- stage B chunk 64 x 32 (512 float4, 2/thread) ----
#pragma unroll
        for (int it = 0; it < 2; ++it) {
            int idx = tid + it * 256;
            int n = idx >> 3, c4 = (idx & 7) << 2;
            float4 v = *(const float4*)(WT + (size_t)(bn + n) * K + k0 + c4);
            *(float4*)&Bs[n * APAD + c4] = v;
        }
        __syncthreads();

        // ---- compute: 4 k-steps of 8 ----
#pragma unroll
        for (int ks = 0; ks < CK; ks += 8) {
            uint32_t a[2][4], b[4][2];
#pragma unroll
            for (int mi = 0; mi < 2; ++mi) {
                int r = wm * 32 + mi * 16 + grp;
                a[mi][0] = __float_as_uint(As[r * APAD + ks + qid]);
                a[mi][1] = __float_as_uint(As[(r + 8) * APAD + ks + qid]);
                a[mi][2] = __float_as_uint(As[r * APAD + ks + qid + 4]);
                a[mi][3] = __float_as_uint(As[(r + 8) * APAD + ks + qid + 4]);
            }
#pragma unroll
            for (int ni = 0; ni < 4; ++ni) {
                int n = wn * 32 + ni * 8 + grp;
                b[ni][0] = __float_as_uint(Bs[n * APAD + ks + qid]);
                b[ni][1] = __float_as_uint(Bs[n * APAD + ks + qid + 4]);
            }
#pragma unroll
            for (int mi = 0; mi < 2; ++mi)
#pragma unroll
                for (int ni = 0; ni < 4; ++ni)
                    mma_tf32(d[mi][ni], a[mi], b[ni]);
        }
        __syncthreads();
    }

    // ---- epilogue ----
    float ask = 0.0f;
    if (SKIP) ask = 1.0f / (1.0f + expf(-*skip_p));
#pragma unroll
    for (int mi = 0; mi < 2; ++mi) {
#pragma unroll
        for (int ni = 0; ni < 4; ++ni) {
            int r0 = bm + wm * 32 + mi * 16 + grp;
            int col = bn + wn * 32 + ni * 8 + 2 * qid;
            float b0 = bias[col], b1 = bias[col + 1];
#pragma unroll
            for (int half = 0; half < 2; ++half) {
                int gr = r0 + half * 8;
                if (gr >= M) continue;
                float v0 = d[mi][ni][2 * half + 0] + b0;
                float v1 = d[mi][ni][2 * half + 1] + b1;
                if (RELU) { v0 = fmaxf(v0, 0.0f); v1 = fmaxf(v1, 0.0f); }
                if (SKIP) {
                    const float* xp = Xprev + (size_t)gr * ldx + col;
                    v0 = ask * v0 + (1.0f - ask) * xp[0];
                    v1 = ask * v1 + (1.0f - ask) * xp[1];
                }
                *(float2*)(C + (size_t)gr * ldc + col) = make_float2(v0, v1);
            }
        }
    }
}

// ---------------- transpose + tf32 round: WT[n*K+k] = tf32(W[k*N+n]) ------
__global__ void transpose_tf32_kernel(const float* __restrict__ W,
                                      float* __restrict__ WT, int K, int N)
{
    int idx = blockIdx.x * blockDim.x + threadIdx.x;
    if (idx >= K * N) return;
    int n = idx / K, k = idx - n * K;
    WT[idx] = tf32r(W[(size_t)k * N + n]);
}

// ---------------- weight-folding kernels ----------------
__global__ void copy_q_kernel(const float* __restrict__ w, const float* __restrict__ b,
                              float* __restrict__ Wcat, float* __restrict__ bcat,
                              int F, int F3, int ncols)
{
    int idx = blockIdx.x * blockDim.x + threadIdx.x;
    int total = (HID + 1) * F;
    if (idx >= total) return;
    int i = idx / F, c = idx - (idx / F) * F;
    if (i < HID) Wcat[i * ncols + c] = w[i * F3 + F + c];
    else         bcat[c] = b[F + c];
}

__global__ void build_rel_kernel(const float* __restrict__ w, const float* __restrict__ b,
                                 const float* __restrict__ rel,
                                 float* __restrict__ Wcat, float* __restrict__ bcat,
                                 int F, int F3, int ncols, int cb)
{
    int idx = blockIdx.x * blockDim.x + threadIdx.x;
    int total = (HID + 1) * F;
    if (idx >= total) return;
    int i = idx / F, c = idx - (idx / F) * F;
    int h = c >> 4, j = c & 15;
    const float* src = (i < HID) ? (w + i * F3 + cb) : (b + cb);
    const float* rm = rel + h * 256 + j;
    float acc = 0.0f;
#pragma unroll
    for (int d = 0; d < 16; ++d) acc += src[h * 16 + d] * rm[d * 16];
    if (i < HID) Wcat[i * ncols + c] = acc;
    else         bcat[c] = acc;
}

__global__ void fill_kernel(float* __restrict__ p, float v, int n)
{
    int i = blockIdx.x * blockDim.x + threadIdx.x;
    if (i < n) p[i] = v;
}

// ---------------- edge kernels ----------------
__global__ void score_kernel(const int* __restrict__ ei, int E,
                             const float* __restrict__ qb, int ldq,
                             const float* __restrict__ kb, int ldk,
                             const float* __restrict__ prel, int H,
                             float* __restrict__ sc, float* __restrict__ mbuf)
{
    int idx = blockIdx.x * blockDim.x + threadIdx.x;
    if (idx >= E * H) return;
    int e = idx / H, h = idx - e * H;
    int src = ei[e], dst = ei[E + e];
    const float4* q = (const float4*)(qb + (size_t)dst * ldq + h * 16);
    const float4* k = (const float4*)(kb + (size_t)src * ldk + h * 16);
    float s = 0.0f;
#pragma unroll
    for (int r = 0; r < 4; ++r) {
        float4 a = q[r], b = k[r];
        s += a.x * b.x + a.y * b.y + a.z * b.z + a.w * b.w;
    }
    s *= prel[h] * 0.25f;
    sc[idx] = s;
    atomic_max_f(&mbuf[(size_t)dst * H + h], s);
}

__global__ void expden_kernel(const int* __restrict__ ei, int E, int H,
                              const float* __restrict__ mbuf,
                              float* __restrict__ sc, float* __restrict__ den)
{
    int idx = blockIdx.x * blockDim.x + threadIdx.x;
    if (idx >= E * H) return;
    int e = idx / H, h = idx - e * H;
    int dst = ei[E + e];
    float ex = expf(sc[idx] - mbuf[(size_t)dst * H + h]);
    sc[idx] = ex;
    atomicAdd(&den[(size_t)dst * H + h], ex);
}

__global__ void agg_kernel(const int* __restrict__ ei, int E, int H, int F,
                           const float* __restrict__ vb, int ldv,
                           const float* __restrict__ sc, const float* __restrict__ den,
                           float* __restrict__ agg)
{
    int f4n = F >> 2;
    int idx = blockIdx.x * blockDim.x + threadIdx.x;
    if (idx >= E * f4n) return;
    int e = idx / f4n, f4 = idx - e * f4n;
    int h = f4 >> 2;
    int src = ei[e], dst = ei[E + e];
    float alpha = sc[(size_t)e * H + h] / fmaxf(den[(size_t)dst * H + h], 1e-16f);
    float4 v = *(const float4*)(vb + (size_t)src * ldv + f4 * 4);
    float* p = agg + (size_t)dst * F + f4 * 4;
    atomicAdd(p + 0, v.x * alpha);
    atomicAdd(p + 1, v.y * alpha);
    atomicAdd(p + 2, v.z * alpha);
    atomicAdd(p + 3, v.w * alpha);
}

// ---------------- host side ----------------
struct Scratch {
    float *XS0, *XS1, *CAT, *SC, *M, *DEN, *AGG, *WCAT, *BCAT, *WT;
};

template <int PRE, int RELU, int SKIP>
static void launch_gemm(const float* A, int lda, const float* WT, int K,
                        const float* bias, float* C, int ldc, int M, int N,
                        const float* skip_p, const float* Xprev, int ldx)
{
    dim3 g((M + 127) / 128, N / 64);
    mma_gemm<PRE, RELU, SKIP><<<g, 256>>>(A, lda, WT, K, bias, C, ldc, M,
                                          skip_p, Xprev, ldx);
}

static void run_hgt_layer(const Scratch& S,
                          int F, int H,
                          const float* kqvw, const float* kqvb,
                          const float* krel, const float* vrel,
                          const float* prel, const float* outw, const float* outb,
                          const float* skip,
                          const float* xs_in, float* out_base, bool final_layer,
                          const int* const* EIp)
{
    const int F3 = 3 * F;
    const int ncols[3] = {5 * F, 5 * F, 3 * F};
    const size_t cbase[3] = {0,
                             (size_t)N0 * ncols[0],
                             (size_t)N0 * ncols[0] + (size_t)N1 * ncols[1]};
    const int wbase[3] = {0, HID * ncols[0], HID * (ncols[0] + ncols[1])};
    const int bbase[3] = {0, ncols[0], ncols[0] + ncols[1]};
    const int koff_e[5] = {F, F, 3 * F, 3 * F, F};

    // 1. build concatenated [q | k_rel | v_rel] weights
    {
        int tot = (HID + 1) * F;
        int blk = (tot + 255) / 256;
        for (int t = 0; t < 3; ++t)
            copy_q_kernel<<<blk, 256>>>(kqvw + (size_t)t * HID * F3, kqvb + (size_t)t * F3,
                                        S.WCAT + wbase[t], S.BCAT + bbase[t],
                                        F, F3, ncols[t]);
        for (int e = 0; e < 5; ++e) {
            int t = EDGE_SRC[e];
            build_rel_kernel<<<blk, 256>>>(kqvw + (size_t)t * HID * F3, kqvb + (size_t)t * F3,
                                           krel + (size_t)e * H * 256,
                                           S.WCAT + wbase[t] + koff_e[e],
                                           S.BCAT + bbase[t] + koff_e[e],
                                           F, F3, ncols[t], 0);
            build_rel_kernel<<<blk, 256>>>(kqvw + (size_t)t * HID * F3, kqvb + (size_t)t * F3,
                                           vrel + (size_t)e * H * 256,
                                           S.WCAT + wbase[t] + koff_e[e] + F,
                                           S.BCAT + bbase[t] + koff_e[e] + F,
                                           F, F3, ncols[t], 2 * F);
        }
    }

    // 1b. transpose WCAT blocks -> WT (tf32)
    for (int t = 0; t < 3; ++t) {
        int tot = HID * ncols[t];
        transpose_tf32_kernel<<<(tot + 255) / 256, 256>>>(
            S.WCAT + wbase[t], S.WT + (size_t)bbase[t] * HID, HID, ncols[t]);
    }

    // 2. fused KQV+relation GEMMs (tensor cores)
    for (int t = 0; t < 3; ++t) {
        const float* A = xs_in + (size_t)NODE_OFF_[t] * HID;
        const float* WTp = S.WT + (size_t)bbase[t] * HID;
        float* Cp = S.CAT + cbase[t];
        launch_gemm<0, 0, 0>(A, HID, WTp, HID, S.BCAT + bbase[t],
                             Cp, ncols[t], NODE_N_[t], ncols[t],
                             nullptr, nullptr, 0);
    }

    // 3. init softmax state
    {
        int n1 = NTOT * H;
        fill_kernel<<<(n1 + 255) / 256, 256>>>(S.M, -FLT_MAX, n1);
        fill_kernel<<<(n1 + 255) / 256, 256>>>(S.DEN, 0.0f, n1);
        int n2 = NTOT * F;
        fill_kernel<<<(n2 + 255) / 256, 256>>>(S.AGG, 0.0f, n2);
    }

    // 4. edge passes
    for (int e = 0; e < 5; ++e) {
        int ts = EDGE_SRC[e], td = EDGE_DST[e], E = EDGE_CNT[e];
        int n = E * H;
        score_kernel<<<(n + 255) / 256, 256>>>(
            EIp[e], E,
            S.CAT + cbase[td], ncols[td],
            S.CAT + cbase[ts] + koff_e[e], ncols[ts],
            prel + (size_t)e * H, H,
            S.SC + (size_t)EOFF[e] * H,
            S.M + (size_t)NODE_OFF_[td] * H);
    }
    for (int e = 0; e < 5; ++e) {
        int td = EDGE_DST[e], E = EDGE_CNT[e];
        int n = E * H;
        expden_kernel<<<(n + 255) / 256, 256>>>(
            EIp[e], E, H,
            S.M + (size_t)NODE_OFF_[td] * H,
            S.SC + (size_t)EOFF[e] * H,
            S.DEN + (size_t)NODE_OFF_[td] * H);
    }
    for (int e = 0; e < 5; ++e) {
        int ts = EDGE_SRC[e], td = EDGE_DST[e], E = EDGE_CNT[e];
        int n = E * (F / 4);
        agg_kernel<<<(n + 255) / 256, 256>>>(
            EIp[e], E, H, F,
            S.CAT + cbase[ts] + koff_e[e] + F, ncols[ts],
            S.SC + (size_t)EOFF[e] * H,
            S.DEN + (size_t)NODE_OFF_[td] * H,
            S.AGG + (size_t)NODE_OFF_[td] * F);
    }

    // 5. output projection: gelu(agg) @ out_w + b (+ skip blend on layer 1)
    for (int t = 0; t < 3; ++t) {
        int tot = F * F;
        transpose_tf32_kernel<<<(tot + 255) / 256, 256>>>(
            outw + (size_t)t * F * F, S.WT + (size_t)t * F * F, F, F);
    }
    for (int t = 0; t < 3; ++t) {
        const float* A = S.AGG + (size_t)NODE_OFF_[t] * F;
        const float* WTp = S.WT + (size_t)t * F * F;
        if (!final_layer) {
            launch_gemm<1, 0, 1>(A, F, WTp, F, outb + (size_t)t * F,
                                 out_base + (size_t)NODE_OFF_[t] * HID, HID,
                                 NODE_N_[t], F,
                                 skip + t, xs_in + (size_t)NODE_OFF_[t] * HID, HID);
        } else {
            launch_gemm<1, 0, 0>(A, F, WTp, F, outb + (size_t)t * F,
                                 out_base + (size_t)NODE_OFF_[t] * F, F,
                                 NODE_N_[t], F,
                                 nullptr, nullptr, 0);
        }
    }
}

// ---------------- entry point ----------------
extern "C" void kernel_launch(void* const* d_in, const int* in_sizes, int n_in,
                              void* d_out, int out_size)
{
    int xp, xa, xi, lwp, lbp, lwa, lba, lwi, lbi;
    int kw1, kb1, kr1, vr1, pr1, ow1, ob1, sk1;
    int kw2, kb2, kr2, vr2, pr2, ow2, ob2, sk2;
    int eix[5];
    if (n_in > 3 && in_sizes[3] == 32768) {
        xp = 0; xa = 1; xi = 2;
        lwp = 3; lbp = 4; lwa = 5; lba = 6; lwi = 7; lbi = 8;
        kw1 = 9; kb1 = 10; kr1 = 11; vr1 = 12; pr1 = 13; ow1 = 14; ob1 = 15; sk1 = 16;
        kw2 = 17; kb2 = 18; kr2 = 19; vr2 = 20; pr2 = 21; ow2 = 22; ob2 = 23; sk2 = 24;
        eix[0] = 25; eix[1] = 26; eix[2] = 27; eix[3] = 28; eix[4] = 29;
    } else {
        xp = 0; xa = 1; xi = 2;
        eix[0] = 3; eix[1] = 4; eix[2] = 5; eix[3] = 6; eix[4] = 7;
        lwp = 8; lbp = 9; lwa = 10; lba = 11; lwi = 12; lbi = 13;
        kw1 = 14; kb1 = 15; kr1 = 16; vr1 = 17; pr1 = 18; ow1 = 19; ob1 = 20; sk1 = 21;
        kw2 = 22; kb2 = 23; kr2 = 24; vr2 = 25; pr2 = 26; ow2 = 27; ob2 = 28; sk2 = 29;
    }

    Scratch S;
    cudaGetSymbolAddress((void**)&S.XS0, g_XS0);
    cudaGetSymbolAddress((void**)&S.XS1, g_XS1);
    cudaGetSymbolAddress((void**)&S.CAT, g_CAT);
    cudaGetSymbolAddress((void**)&S.SC,  g_SC);
    cudaGetSymbolAddress((void**)&S.M,   g_M);
    cudaGetSymbolAddress((void**)&S.DEN, g_DEN);
    cudaGetSymbolAddress((void**)&S.AGG, g_AGG);
    cudaGetSymbolAddress((void**)&S.WCAT, g_WCAT);
    cudaGetSymbolAddress((void**)&S.BCAT, g_BCAT);
    cudaGetSymbolAddress((void**)&S.WT,   g_WT);

    const float* X[3]  = {(const float*)d_in[xp], (const float*)d_in[xa], (const float*)d_in[xi]};
    const float* LW[3] = {(const float*)d_in[lwp], (const float*)d_in[lwa], (const float*)d_in[lwi]};
    const float* LB[3] = {(const float*)d_in[lbp], (const float*)d_in[lba], (const float*)d_in[lbi]};
    const int* EIp[5];
    for (int e = 0; e < 5; ++e) EIp[e] = (const int*)d_in[eix[e]];

    // input projections + relu -> XS0 (tensor cores)
    const int lwt_off[3] = {0, 32768, 49152};   // 128*256, +128*128
    for (int t = 0; t < 3; ++t) {
        int tot = IN_DIM_[t] * HID;
        transpose_tf32_kernel<<<(tot + 255) / 256, 256>>>(
            LW[t], S.WT + lwt_off[t], IN_DIM_[t], HID);
    }
    for (int t = 0; t < 3; ++t) {
        launch_gemm<0, 1, 0>(X[t], IN_DIM_[t], S.WT + lwt_off[t], IN_DIM_[t],
                             LB[t], S.XS0 + (size_t)NODE_OFF_[t] * HID, HID,
                             NODE_N_[t], HID, nullptr, nullptr, 0);
    }

    // layer 1: hidden 128, heads 8, skip blend, XS0 -> XS1
    run_hgt_layer(S, 128, 8,
                  (const float*)d_in[kw1], (const float*)d_in[kb1],
                  (const float*)d_in[kr1], (const float*)d_in[vr1],
                  (const float*)d_in[pr1], (const float*)d_in[ow1],
                  (const float*)d_in[ob1], (const float*)d_in[sk1],
                  S.XS0, S.XS1, false, EIp);

    // layer 2: out 64, heads 4, no skip, XS1 -> d_out
    run_hgt_layer(S, 64, 4,
                  (const float*)d_in[kw2], (const float*)d_in[kb2],
                  (const float*)d_in[kr2], (const float*)d_in[vr2],
                  (const float*)d_in[pr2], (const float*)d_in[ow2],
                  (const float*)d_in[ob2], (const float*)d_in[sk2],
                  S.XS1, (float*)d_out, true, EIp);

    (void)out_size;
}

// round 7
// speedup vs baseline: 1.6830x; 1.1517x over previous
#include <cuda_runtime.h>
#include <math.h>
#include <float.h>
#include <stdint.h>

#define HID 128

// ---------------- problem constants ----------------
#define N0 100000
#define N1 50000
#define N2 5000
#define NTOT (N0 + N1 + N2)
#define ETOT 900000

static const int EDGE_SRC[5] = {1, 0, 0, 1, 2};
static const int EDGE_DST[5] = {0, 0, 1, 2, 1};
static const int EDGE_CNT[5] = {250000, 250000, 200000, 100000, 100000};
static const int EOFF[5]     = {0, 250000, 500000, 700000, 800000};
static const int NODE_N_[3]  = {N0, N1, N2};
static const int NODE_OFF_[3]= {0, N0, N0 + N1};
static const int IN_DIM_[3]  = {256, 128, 64};

// ---------------- device scratch ----------------
__device__ float g_XS0[(size_t)NTOT * HID];
__device__ float g_XS1[(size_t)NTOT * HID];
__device__ float g_CAT[(size_t)N0 * 640 + (size_t)N1 * 640 + (size_t)N2 * 384];
__device__ float g_SC [(size_t)ETOT * 8];
__device__ float g_M  [(size_t)NTOT * 8];
__device__ float g_DEN[(size_t)NTOT * 8];
__device__ float g_AGG[(size_t)NTOT * 128];
__device__ float g_WCAT[HID * 1664];
__device__ float g_BCAT[1664];
__device__ float g_WT[262144];   // transposed tf32 weights, reused sequentially

// ---------------- device helpers ----------------
__device__ __forceinline__ float gelu_f(float x) {
    return 0.5f * x * (1.0f + erff(x * 0.70710678118654752440f));
}
__device__ __forceinline__ float tf32r(float x) {
    float y;
    asm("cvt.rna.tf32.f32 %0, %1;" : "=f"(y) : "f"(x));
    return y;
}
__device__ __forceinline__ void atomic_max_f(float* addr, float v) {
    if (v >= 0.0f) atomicMax((int*)addr, __float_as_int(v));
    else           atomicMin((unsigned int*)addr, __float_as_uint(v));
}
__device__ __forceinline__ void red_add_v4(float* p, float4 v) {
    asm volatile("red.global.add.v4.f32 [%0], {%1, %2, %3, %4};"
                 :: "l"(p), "f"(v.x), "f"(v.y), "f"(v.z), "f"(v.w) : "memory");
}

__device__ __forceinline__ void mma_tf32(float* d, const uint32_t* a, const uint32_t* b) {
    asm volatile(
        "mma.sync.aligned.m16n8k8.row.col.f32.tf32.tf32.f32 "
        "{%0,%1,%2,%3}, {%4,%5,%6,%7}, {%8,%9}, {%0,%1,%2,%3};\n"
        : "+f"(d[0]), "+f"(d[1]), "+f"(d[2]), "+f"(d[3])
        : "r"(a[0]), "r"(a[1]), "r"(a[2]), "r"(a[3]), "r"(b[0]), "r"(b[1]));
}

// ---------------- tf32 mma.sync GEMM ----------------
// C[M,N] = epi( preact(A[M,K]) @ WT^T + bias ), WT is [N,K] tf32-rounded.
// CTA tile 128 x NT (NT = 64 or 128), 8 warps. K chunked at 32.
// NT=64 : warp grid 4x2, warp tile 32x32 (MI=2)
// NT=128: warp grid 2x4, warp tile 64x32 (MI=4)
#define CK 32
#define APAD 36

template <int NT, int PRE_GELU, int RELU, int SKIP>
__global__ __launch_bounds__(256)
void mma_gemm(const float* __restrict__ A, int lda,
              const float* __restrict__ WT, int K,
              const float* __restrict__ bias,
              float* __restrict__ C, int ldc, int M,
              const float* __restrict__ skip_p,
              const float* __restrict__ Xprev, int ldx)
{
    constexpr int WCOLS = NT / 32;        // warps along N
    constexpr int WROWS = 8 / WCOLS;      // warps along M
    constexpr int MI = 128 / (16 * WROWS);
    constexpr int NI = 4;

    __shared__ float As[128 * APAD];
    __shared__ float Bs[NT * APAD];
    const int tid = threadIdx.x;
    const int wid = tid >> 5, lane = tid & 31;
    const int grp = lane >> 2, qid = lane & 3;
    const int wm = wid % WROWS, wn = wid / WROWS;
    const int bm = blockIdx.x * 128, bn = blockIdx.y * NT;

    float d[MI][NI][4];
#pragma unroll
    for (int mi = 0; mi < MI; ++mi)
#pragma unroll
        for (int ni = 0; ni < NI; ++ni)
#pragma unroll
            for (int q = 0; q < 4; ++q) d[mi][ni][q] = 0.0f;

    for (int k0 = 0; k0 < K; k0 += CK) {
        // ---- stage A chunk 128 x 32 (1024 float4, 4/thread) ----
#pragma unroll
        for (int it = 0; it < 4; ++it) {
            int idx = tid + it * 256;
            int r = idx >> 3, c4 = (idx & 7) << 2;
            float4 v = make_float4(0.f, 0.f, 0.f, 0.f);
            int gr = bm + r;
            if (gr < M) v = *(const float4*)(A + (size_t)gr * lda + k0 + c4);
            if (PRE_GELU) {
                v.x = gelu_f(v.x); v.y = gelu_f(v.y);
                v.z = gelu_f(v.z); v.w = gelu_f(v.w);
            }
            v.x = tf32r(v.x); v.y = tf32r(v.y); v.z = tf32r(v.z); v.w = tf32r(v.w);
            *(float4*)&As[r * APAD + c4] = v;
        }
        // ---- stage B chunk NT x 32 ----
#pragma unroll
        for (int it = 0; it < NT / 32; ++it) {
            int idx = tid + it * 256;
            int n = idx >> 3, c4 = (idx & 7) << 2;
            float4 v = *(const float4*)(WT + (size_t)(bn + n) * K + k0 + c4);
            *(float4*)&Bs[n * APAD + c4] = v;
        }
        __syncthreads();

        // ---- compute: 4 k-steps of 8 ----
#pragma unroll
        for (int ks = 0; ks < CK; ks += 8) {
            uint32_t a[MI][4], b[NI][2];
#pragma unroll
            for (int mi = 0; mi < MI; ++mi) {
                int r = wm * (16 * MI) + mi * 16 + grp;
                a[mi][0] = __float_as_uint(As[r * APAD + ks + qid]);
                a[mi][1] = __float_as_uint(As[(r + 8) * APAD + ks + qid]);
                a[mi][2] = __float_as_uint(As[r * APAD + ks + qid + 4]);
                a[mi][3] = __float_as_uint(As[(r + 8) * APAD + ks + qid + 4]);
            }
#pragma unroll
            for (int ni = 0; ni < NI; ++ni) {
                int n = wn * 32 + ni * 8 + grp;
                b[ni][0] = __float_as_uint(Bs[n * APAD + ks + qid]);
                b[ni][1] = __float_as_uint(Bs[n * APAD + ks + qid + 4]);
            }
#pragma unroll
            for (int mi = 0; mi < MI; ++mi)
#pragma unroll
                for (int ni = 0; ni < NI; ++ni)
                    mma_tf32(d[mi][ni], a[mi], b[ni]);
        }
        __syncthreads();
    }

    // ---- epilogue ----
    float ask = 0.0f;
    if (SKIP) ask = 1.0f / (1.0f + expf(-*skip_p));
#pragma unroll
    for (int mi = 0; mi < MI; ++mi) {
#pragma unroll
        for (int ni = 0; ni < NI; ++ni) {
            int r0 = bm + wm * (16 * MI) + mi * 16 + grp;
            int col = bn + wn * 32 + ni * 8 + 2 * qid;
            float b0 = bias[col], b1 = bias[col + 1];
#pragma unroll
            for (int half = 0; half < 2; ++half) {
                int gr = r0 + half * 8;
                if (gr >= M) continue;
                float v0 = d[mi][ni][2 * half + 0] + b0;
                float v1 = d[mi][ni][2 * half + 1] + b1;
                if (RELU) { v0 = fmaxf(v0, 0.0f); v1 = fmaxf(v1, 0.0f); }
                if (SKIP) {
                    const float* xp = Xprev + (size_t)gr * ldx + col;
                    v0 = ask * v0 + (1.0f - ask) * xp[0];
                    v1 = ask * v1 + (1.0f - ask) * xp[1];
                }
                *(float2*)(C + (size_t)gr * ldc + col) = make_float2(v0, v1);
            }
        }
    }
}

// ---------------- transpose + tf32 round: WT[n*K+k] = tf32(W[k*N+n]) ------
__global__ void transpose_tf32_kernel(const float* __restrict__ W,
                                      float* __restrict__ WT, int K, int N)
{
    int idx = blockIdx.x * blockDim.x + threadIdx.x;
    if (idx >= K * N) return;
    int n = idx / K, k = idx - n * K;
    WT[idx] = tf32r(W[(size_t)k * N + n]);
}

// ---------------- weight-folding kernels ----------------
__global__ void copy_q_kernel(const float* __restrict__ w, const float* __restrict__ b,
                              float* __restrict__ Wcat, float* __restrict__ bcat,
                              int F, int F3, int ncols)
{
    int idx = blockIdx.x * blockDim.x + threadIdx.x;
    int total = (HID + 1) * F;
    if (idx >= total) return;
    int i = idx / F, c = idx - (idx / F) * F;
    if (i < HID) Wcat[i * ncols + c] = w[i * F3 + F + c];
    else         bcat[c] = b[F + c];
}

__global__ void build_rel_kernel(const float* __restrict__ w, const float* __restrict__ b,
                                 const float* __restrict__ rel,
                                 float* __restrict__ Wcat, float* __restrict__ bcat,
                                 int F, int F3, int ncols, int cb)
{
    int idx = blockIdx.x * blockDim.x + threadIdx.x;
    int total = (HID + 1) * F;
    if (idx >= total) return;
    int i = idx / F, c = idx - (idx / F) * F;
    int h = c >> 4, j = c & 15;
    const float* src = (i < HID) ? (w + i * F3 + cb) : (b + cb);
    const float* rm = rel + h * 256 + j;
    float acc = 0.0f;
#pragma unroll
    for (int d = 0; d < 16; ++d) acc += src[h * 16 + d] * rm[d * 16];
    if (i < HID) Wcat[i * ncols + c] = acc;
    else         bcat[c] = acc;
}

__global__ void fill_kernel(float* __restrict__ p, float v, int n)
{
    int i = blockIdx.x * blockDim.x + threadIdx.x;
    if (i < n) p[i] = v;
}

// ---------------- edge kernels ----------------
__global__ void score_kernel(const int* __restrict__ ei, int E,
                             const float* __restrict__ qb, int ldq,
                             const float* __restrict__ kb, int ldk,
                             const float* __restrict__ prel, int H,
                             float* __restrict__ sc, float* __restrict__ mbuf)
{
    int idx = blockIdx.x * blockDim.x + threadIdx.x;
    if (idx >= E * H) return;
    int e = idx / H, h = idx - e * H;
    int src = ei[e], dst = ei[E + e];
    const float4* q = (const float4*)(qb + (size_t)dst * ldq + h * 16);
    const float4* k = (const float4*)(kb + (size_t)src * ldk + h * 16);
    float s = 0.0f;
#pragma unroll
    for (int r = 0; r < 4; ++r) {
        float4 a = q[r], b = k[r];
        s += a.x * b.x + a.y * b.y + a.z * b.z + a.w * b.w;
    }
    s *= prel[h] * 0.25f;
    sc[idx] = s;
    atomic_max_f(&mbuf[(size_t)dst * H + h], s);
}

// 4 heads per thread; one v4 reduction to den
__global__ void expden_kernel(const int* __restrict__ ei, int E, int H,
                              const float* __restrict__ mbuf,
                              float* __restrict__ sc, float* __restrict__ den)
{
    int g = H >> 2;
    int idx = blockIdx.x * blockDim.x + threadIdx.x;
    if (idx >= E * g) return;
    int e = idx / g, hq = idx - e * g;
    int dst = ei[E + e];
    float4 s = *(float4*)(sc + (size_t)e * H + hq * 4);
    float4 m = *(const float4*)(mbuf + (size_t)dst * H + hq * 4);
    s.x = expf(s.x - m.x); s.y = expf(s.y - m.y);
    s.z = expf(s.z - m.z); s.w = expf(s.w - m.w);
    *(float4*)(sc + (size_t)e * H + hq * 4) = s;
    red_add_v4(den + (size_t)dst * H + hq * 4, s);
}

__global__ void agg_kernel(const int* __restrict__ ei, int E, int H, int F,
                           const float* __restrict__ vb, int ldv,
                           const float* __restrict__ sc, const float* __restrict__ den,
                           float* __restrict__ agg)
{
    int f4n = F >> 2;
    int idx = blockIdx.x * blockDim.x + threadIdx.x;
    if (idx >= E * f4n) return;
    int e = idx / f4n, f4 = idx - e * f4n;
    int h = f4 >> 2;
    int src = ei[e], dst = ei[E + e];
    float alpha = sc[(size_t)e * H + h] / fmaxf(den[(size_t)dst * H + h], 1e-16f);
    float4 v = *(const float4*)(vb + (size_t)src * ldv + f4 * 4);
    red_add_v4(agg + (size_t)dst * F + f4 * 4,
               make_float4(v.x * alpha, v.y * alpha, v.z * alpha, v.w * alpha));
}

// ---------------- host side ----------------
struct Scratch {
    float *XS0, *XS1, *CAT, *SC, *M, *DEN, *AGG, *WCAT, *BCAT, *WT;
};

template <int PRE, int RELU, int SKIP>
static void launch_gemm(const float* A, int lda, const float* WT, int K,
                        const float* bias, float* C, int ldc, int M, int N,
                        const float* skip_p, const float* Xprev, int ldx)
{
    if (N % 128 == 0) {
        dim3 g((M + 127) / 128, N / 128);
        mma_gemm<128, PRE, RELU, SKIP><<<g, 256>>>(A, lda, WT, K, bias, C, ldc, M,
                                                   skip_p, Xprev, ldx);
    } else {
        dim3 g((M + 127) / 128, N / 64);
        mma_gemm<64, PRE, RELU, SKIP><<<g, 256>>>(A, lda, WT, K, bias, C, ldc, M,
                                                  skip_p, Xprev, ldx);
    }
}

static void run_hgt_layer(const Scratch& S,
                          int F, int H,
                          const float* kqvw, const float* kqvb,
                          const float* krel, const float* vrel,
                          const float* prel, const float* outw, const float* outb,
                          const float* skip,
                          const float* xs_in, float* out_base, bool final_layer,
                          const int* const* EIp)
{
    const int F3 = 3 * F;
    const int ncols[3] = {5 * F, 5 * F, 3 * F};
    const size_t cbase[3] = {0,
                             (size_t)N0 * ncols[0],
                             (size_t)N0 * ncols[0] + (size_t)N1 * ncols[1]};
    const int wbase[3] = {0, HID * ncols[0], HID * (ncols[0] + ncols[1])};
    const int bbase[3] = {0, ncols[0], ncols[0] + ncols[1]};
    const int koff_e[5] = {F, F, 3 * F, 3 * F, F};

    // 1. build concatenated [q | k_rel | v_rel] weights
    {
        int tot = (HID + 1) * F;
        int blk = (tot + 255) / 256;
        for (int t = 0; t < 3; ++t)
            copy_q_kernel<<<blk, 256>>>(kqvw + (size_t)t * HID * F3, kqvb + (size_t)t * F3,
                                        S.WCAT + wbase[t], S.BCAT + bbase[t],
                                        F, F3, ncols[t]);
        for (int e = 0; e < 5; ++e) {
            int t = EDGE_SRC[e];
            build_rel_kernel<<<blk, 256>>>(kqvw + (size_t)t * HID * F3, kqvb + (size_t)t * F3,
                                           krel + (size_t)e * H * 256,
                                           S.WCAT + wbase[t] + koff_e[e],
                                           S.BCAT + bbase[t] + koff_e[e],
                                           F, F3, ncols[t], 0);
            build_rel_kernel<<<blk, 256>>>(kqvw + (size_t)t * HID * F3, kqvb + (size_t)t * F3,
                                           vrel + (size_t)e * H * 256,
                                           S.WCAT + wbase[t] + koff_e[e] + F,
                                           S.BCAT + bbase[t] + koff_e[e] + F,
                                           F, F3, ncols[t], 2 * F);
        }
    }

    // 1b. transpose WCAT blocks -> WT (tf32)
    for (int t = 0; t < 3; ++t) {
        int tot = HID * ncols[t];
        transpose_tf32_kernel<<<(tot + 255) / 256, 256>>>(
            S.WCAT + wbase[t], S.WT + (size_t)bbase[t] * HID, HID, ncols[t]);
    }

    // 2. fused KQV+relation GEMMs (tensor cores)
    for (int t = 0; t < 3; ++t) {
        const float* A = xs_in + (size_t)NODE_OFF_[t] * HID;
        const float* WTp = S.WT + (size_t)bbase[t] * HID;
        float* Cp = S.CAT + cbase[t];
        launch_gemm<0, 0, 0>(A, HID, WTp, HID, S.BCAT + bbase[t],
                             Cp, ncols[t], NODE_N_[t], ncols[t],
                             nullptr, nullptr, 0);
    }

    // 3. init softmax state
    {
        int n1 = NTOT * H;
        fill_kernel<<<(n1 + 255) / 256, 256>>>(S.M, -FLT_MAX, n1);
        fill_kernel<<<(n1 + 255) / 256, 256>>>(S.DEN, 0.0f, n1);
        int n2 = NTOT * F;
        fill_kernel<<<(n2 + 255) / 256, 256>>>(S.AGG, 0.0f, n2);
    }

    // 4. edge passes
    for (int e = 0; e < 5; ++e) {
        int ts = EDGE_SRC[e], td = EDGE_DST[e], E = EDGE_CNT[e];
        int n = E * H;
        score_kernel<<<(n + 255) / 256, 256>>>(
            EIp[e], E,
            S.CAT + cbase[td], ncols[td],
            S.CAT + cbase[ts] + koff_e[e], ncols[ts],
            prel + (size_t)e * H, H,
            S.SC + (size_t)EOFF[e] * H,
            S.M + (size_t)NODE_OFF_[td] * H);
    }
    for (int e = 0; e < 5; ++e) {
        int td = EDGE_DST[e], E = EDGE_CNT[e];
        int n = E * (H >> 2);
        expden_kernel<<<(n + 255) / 256, 256>>>(
            EIp[e], E, H,
            S.M + (size_t)NODE_OFF_[td] * H,
            S.SC + (size_t)EOFF[e] * H,
            S.DEN + (size_t)NODE_OFF_[td] * H);
    }
    for (int e = 0; e < 5; ++e) {
        int ts = EDGE_SRC[e], td = EDGE_DST[e], E = EDGE_CNT[e];
        int n = E * (F / 4);
        agg_kernel<<<(n + 255) / 256, 256>>>(
            EIp[e], E, H, F,
            S.CAT + cbase[ts] + koff_e[e] + F, ncols[ts],
            S.SC + (size_t)EOFF[e] * H,
            S.DEN + (size_t)NODE_OFF_[td] * H,
            S.AGG + (size_t)NODE_OFF_[td] * F);
    }

    // 5. output projection: gelu(agg) @ out_w + b (+ skip blend on layer 1)
    for (int t = 0; t < 3; ++t) {
        int tot = F * F;
        transpose_tf32_kernel<<<(tot + 255) / 256, 256>>>(
            outw + (size_t)t * F * F, S.WT + (size_t)t * F * F, F, F);
    }
    for (int t = 0; t < 3; ++t) {
        const float* A = S.AGG + (size_t)NODE_OFF_[t] * F;
        const float* WTp = S.WT + (size_t)t * F * F;
        if (!final_layer) {
            launch_gemm<1, 0, 1>(A, F, WTp, F, outb + (size_t)t * F,
                                 out_base + (size_t)NODE_OFF_[t] * HID, HID,
                                 NODE_N_[t], F,
                                 skip + t, xs_in + (size_t)NODE_OFF_[t] * HID, HID);
        } else {
            launch_gemm<1, 0, 0>(A, F, WTp, F, outb + (size_t)t * F,
                                 out_base + (size_t)NODE_OFF_[t] * F, F,
                                 NODE_N_[t], F,
                                 nullptr, nullptr, 0);
        }
    }
}

// ---------------- entry point ----------------
extern "C" void kernel_launch(void* const* d_in, const int* in_sizes, int n_in,
                              void* d_out, int out_size)
{
    int xp, xa, xi, lwp, lbp, lwa, lba, lwi, lbi;
    int kw1, kb1, kr1, vr1, pr1, ow1, ob1, sk1;
    int kw2, kb2, kr2, vr2, pr2, ow2, ob2, sk2;
    int eix[5];
    if (n_in > 3 && in_sizes[3] == 32768) {
        xp = 0; xa = 1; xi = 2;
        lwp = 3; lbp = 4; lwa = 5; lba = 6; lwi = 7; lbi = 8;
        kw1 = 9; kb1 = 10; kr1 = 11; vr1 = 12; pr1 = 13; ow1 = 14; ob1 = 15; sk1 = 16;
        kw2 = 17; kb2 = 18; kr2 = 19; vr2 = 20; pr2 = 21; ow2 = 22; ob2 = 23; sk2 = 24;
        eix[0] = 25; eix[1] = 26; eix[2] = 27; eix[3] = 28; eix[4] = 29;
    } else {
        xp = 0; xa = 1; xi = 2;
        eix[0] = 3; eix[1] = 4; eix[2] = 5; eix[3] = 6; eix[4] = 7;
        lwp = 8; lbp = 9; lwa = 10; lba = 11; lwi = 12; lbi = 13;
        kw1 = 14; kb1 = 15; kr1 = 16; vr1 = 17; pr1 = 18; ow1 = 19; ob1 = 20; sk1 = 21;
        kw2 = 22; kb2 = 23; kr2 = 24; vr2 = 25; pr2 = 26; ow2 = 27; ob2 = 28; sk2 = 29;
    }

    Scratch S;
    cudaGetSymbolAddress((void**)&S.XS0, g_XS0);
    cudaGetSymbolAddress((void**)&S.XS1, g_XS1);
    cudaGetSymbolAddress((void**)&S.CAT, g_CAT);
    cudaGetSymbolAddress((void**)&S.SC,  g_SC);
    cudaGetSymbolAddress((void**)&S.M,   g_M);
    cudaGetSymbolAddress((void**)&S.DEN, g_DEN);
    cudaGetSymbolAddress((void**)&S.AGG, g_AGG);
    cudaGetSymbolAddress((void**)&S.WCAT, g_WCAT);
    cudaGetSymbolAddress((void**)&S.BCAT, g_BCAT);
    cudaGetSymbolAddress((void**)&S.WT,   g_WT);

    const float* X[3]  = {(const float*)d_in[xp], (const float*)d_in[xa], (const float*)d_in[xi]};
    const float* LW[3] = {(const float*)d_in[lwp], (const float*)d_in[lwa], (const float*)d_in[lwi]};
    const float* LB[3] = {(const float*)d_in[lbp], (const float*)d_in[lba], (const float*)d_in[lbi]};
    const int* EIp[5];
    for (int e = 0; e < 5; ++e) EIp[e] = (const int*)d_in[eix[e]];

    // input projections + relu -> XS0 (tensor cores)
    const int lwt_off[3] = {0, 32768, 49152};   // 128*256, +128*128
    for (int t = 0; t < 3; ++t) {
        int tot = IN_DIM_[t] * HID;
        transpose_tf32_kernel<<<(tot + 255) / 256, 256>>>(
            LW[t], S.WT + lwt_off[t], IN_DIM_[t], HID);
    }
    for (int t = 0; t < 3; ++t) {
        launch_gemm<0, 1, 0>(X[t], IN_DIM_[t], S.WT + lwt_off[t], IN_DIM_[t],
                             LB[t], S.XS0 + (size_t)NODE_OFF_[t] * HID, HID,
                             NODE_N_[t], HID, nullptr, nullptr, 0);
    }

    // layer 1: hidden 128, heads 8, skip blend, XS0 -> XS1
    run_hgt_layer(S, 128, 8,
                  (const float*)d_in[kw1], (const float*)d_in[kb1],
                  (const float*)d_in[kr1], (const float*)d_in[vr1],
                  (const float*)d_in[pr1], (const float*)d_in[ow1],
                  (const float*)d_in[ob1], (const float*)d_in[sk1],
                  S.XS0, S.XS1, false, EIp);

    // layer 2: out 64, heads 4, no skip, XS1 -> d_out
    run_hgt_layer(S, 64, 4,
                  (const float*)d_in[kw2], (const float*)d_in[kb2],
                  (const float*)d_in[kr2], (const float*)d_in[vr2],
                  (const float*)d_in[pr2], (const float*)d_in[ow2],
                  (const float*)d_in[ob2], (const float*)d_in[sk2],
                  S.XS1, (float*)d_out, true, EIp);

    (void)out_size;
}